// round 5
// baseline (speedup 1.0000x reference)
#include <cuda_runtime.h>
#include <math.h>

#define Bn 32
#define Cn 512
#define HWn 3136
#define NV4 784             // HWn / 4
#define NROWS (Bn * Cn)     // 16384
#define BPC 8               // batches per chunk
#define RPC (BPC * Cn)      // 4096 rows per chunk
#define MEAN_BLOCKS (RPC / 2)   // 2048: each mean block = 2 rows, 4 warps/row

__device__ float g_y[NROWS];

// ---------------------------------------------------------------------------
// Deformable-attention scalar for one (b, p) row. Tiny; L2-hit loads.
// ---------------------------------------------------------------------------
__device__ __forceinline__ float attn_for_row(int row,
                                              const float* __restrict__ w_offset,
                                              const float* __restrict__ w_deform,
                                              const float* __restrict__ b_deform) {
    int b = row >> 9;          // row / Cn
    int p = row & (Cn - 1);
    const float* yb = g_y + b * Cn;
    float acc = b_deform[0];
    #pragma unroll
    for (int k = 0; k < 3; k++) {
        float off = 0.0f;
        #pragma unroll
        for (int j = 0; j < 3; j++) {
            int ii = p + j - 1;
            float yv = (ii >= 0 && ii < Cn) ? yb[ii] : 0.0f;
            off = fmaf(w_offset[k * 3 + j], yv, off);
        }
        float pos = (float)(p + k - 1) + off;
        float p0 = floorf(pos);
        float frac = pos - p0;
        int p0i = (int)p0;
        float v0 = (p0i >= 0     && p0i < Cn)     ? yb[p0i]     : 0.0f;
        float v1 = (p0i + 1 >= 0 && p0i + 1 < Cn) ? yb[p0i + 1] : 0.0f;
        acc = fmaf(w_deform[k], fmaf(v1 - v0, frac, v0), acc);
    }
    return 1.0f / (1.0f + __expf(-acc));
}

// ---------------------------------------------------------------------------
// Fused pipeline stage with per-block work EQUALIZED at ~25 KB of traffic:
//   mean block : 2 rows, 4 warps per row, normal-policy reads (retain in L2)
//   scale block: 1 row, __ldcs reads (L2-hot from prev stage), __stcs writes
// Middle grids interleave (mean, scale, scale) triplets.
// ---------------------------------------------------------------------------
__global__ void fused_kernel(const float* __restrict__ x,
                             float* __restrict__ out,
                             const float* __restrict__ w_offset,
                             const float* __restrict__ w_deform,
                             const float* __restrict__ b_deform,
                             int mean_chunk, int scale_chunk) {
    int bid = blockIdx.x;
    bool do_mean;
    int mean_blk = 0, scale_row = 0;
    if (mean_chunk >= 0 && scale_chunk >= 0) {
        int g = bid / 3, pos = bid - g * 3;        // g: 0..2047
        if (pos == 0) { do_mean = true;  mean_blk  = g; }
        else          { do_mean = false; scale_row = scale_chunk * RPC + g * 2 + (pos - 1); }
    } else if (mean_chunk >= 0) {
        do_mean = true;  mean_blk = bid;
    } else {
        do_mean = false; scale_row = scale_chunk * RPC + bid;
    }

    if (do_mean) {
        // 2 rows per block, 4 warps (128 threads) per row.
        __shared__ float part[8];
        int warp = threadIdx.x >> 5;               // 0..7
        int lane = threadIdx.x & 31;
        int r    = warp >> 2;                      // 0..1
        int q    = warp & 3;                       // quarter within row
        int row  = mean_chunk * RPC + mean_blk * 2 + r;
        const float4* rp = (const float4*)(x + (size_t)row * HWn);
        float s = 0.0f;
        #pragma unroll
        for (int i = q * 32 + lane; i < NV4; i += 128) {
            float4 v = __ldg(&rp[i]);              // retain in L2
            s += (v.x + v.y) + (v.z + v.w);
        }
        #pragma unroll
        for (int o = 16; o > 0; o >>= 1)
            s += __shfl_down_sync(0xffffffffu, s, o);
        if (lane == 0) part[warp] = s;
        __syncthreads();
        if (threadIdx.x < 2) {
            float t = part[threadIdx.x * 4] + part[threadIdx.x * 4 + 1]
                    + part[threadIdx.x * 4 + 2] + part[threadIdx.x * 4 + 3];
            g_y[mean_chunk * RPC + mean_blk * 2 + threadIdx.x] = t * (1.0f / (float)HWn);
        }
        return;
    }

    // ---- scale block ----
    __shared__ float sa;
    if (threadIdx.x == 0)
        sa = attn_for_row(scale_row, w_offset, w_deform, b_deform);
    __syncthreads();
    float a = sa;

    const float4* xin = (const float4*)(x + (size_t)scale_row * HWn);
    float4* o = (float4*)(out + (size_t)scale_row * HWn);
    #pragma unroll 2
    for (int i = threadIdx.x; i < NV4; i += 256) {
        float4 v = __ldcs(&xin[i]);                // dead after this read
        v.x *= a; v.y *= a; v.z *= a; v.w *= a;
        __stcs(&o[i], v);                          // don't evict retained chunk
    }
}

extern "C" void kernel_launch(void* const* d_in, const int* in_sizes, int n_in,
                              void* d_out, int out_size) {
    const float* x        = (const float*)d_in[0];
    const float* w_offset = (const float*)d_in[1];
    const float* w_deform = (const float*)d_in[2];
    const float* b_deform = (const float*)d_in[3];
    float* out = (float*)d_out;

    // Pipeline over 4 chunks of 8 batches:
    //   K0: mean(c0)
    //   K1: mean(c1) || scale(c0)
    //   K2: mean(c2) || scale(c1)
    //   K3: mean(c3) || scale(c2)
    //   K4: scale(c3)
    fused_kernel<<<MEAN_BLOCKS, 256>>>(x, out, w_offset, w_deform, b_deform, 0, -1);
    fused_kernel<<<MEAN_BLOCKS * 3, 256>>>(x, out, w_offset, w_deform, b_deform, 1, 0);
    fused_kernel<<<MEAN_BLOCKS * 3, 256>>>(x, out, w_offset, w_deform, b_deform, 2, 1);
    fused_kernel<<<MEAN_BLOCKS * 3, 256>>>(x, out, w_offset, w_deform, b_deform, 3, 2);
    fused_kernel<<<RPC, 256>>>(x, out, w_offset, w_deform, b_deform, -1, 3);
}